// round 1
// baseline (speedup 1.0000x reference)
#include <cuda_runtime.h>

#define Bn 8
#define C_IN 128
#define C_OUT 128
#define K2 9
#define HH 64
#define WW 64
#define HW 4096
#define NOFF 18

// Scratch (no cudaMalloc allowed)
__device__ float g_xt[Bn * HW * C_IN];       // x transposed: [b][y][x][c]
__device__ float g_wT[K2 * C_IN * C_OUT];    // w_conv transposed: [k][cin][o]
__device__ float g_woT[K2 * C_IN * NOFF];    // w_offset transposed: [k][cin][oc]
__device__ float g_off[Bn * NOFF * HW];      // offset conv output: [b][ch][y][x]

// ---------------------------------------------------------------------------
// NCHW -> NHWC transpose of x (treat as [CIN][HW] -> [HW][CIN] per batch)
// ---------------------------------------------------------------------------
__global__ void transpose_x_kernel(const float* __restrict__ x) {
    __shared__ float tile[32][33];
    int b = blockIdx.z;
    int hw0 = blockIdx.x * 32;
    int c0 = blockIdx.y * 32;
    const float* xb = x + (size_t)b * C_IN * HW;
    #pragma unroll
    for (int i = threadIdx.y; i < 32; i += 8)
        tile[i][threadIdx.x] = xb[(size_t)(c0 + i) * HW + hw0 + threadIdx.x];
    __syncthreads();
    float* xt = g_xt + (size_t)b * HW * C_IN;
    #pragma unroll
    for (int i = threadIdx.y; i < 32; i += 8)
        xt[(size_t)(hw0 + i) * C_IN + c0 + threadIdx.x] = tile[threadIdx.x][i];
}

// ---------------------------------------------------------------------------
// Weight transposes: w_conv (o,cin,k) -> g_wT[k][cin][o]
//                    w_offset (oc,cin,k) -> g_woT[k][cin][oc]
// ---------------------------------------------------------------------------
__global__ void transpose_w_kernel(const float* __restrict__ wo,
                                   const float* __restrict__ wc) {
    int i = blockIdx.x * 256 + threadIdx.x;
    if (i < K2 * C_IN * C_OUT) {
        int o = i & 127;
        int c = (i >> 7) & 127;
        int k = i >> 14;
        g_wT[i] = wc[(o * 128 + c) * 9 + k];
    }
    if (i < K2 * C_IN * NOFF) {
        int oc = i % 18;
        int rem = i / 18;
        int c = rem & 127;
        int k = rem >> 7;
        g_woT[i] = wo[(oc * 128 + c) * 9 + k];
    }
}

// ---------------------------------------------------------------------------
// Offset conv: standard 3x3 conv, 18 output channels, implicit GEMM.
// Block = one (b, row-pair): 128 pixels x 18 outputs. 256 threads.
// ---------------------------------------------------------------------------
__global__ __launch_bounds__(256) void offset_conv_kernel() {
    __shared__ float a_s[128][33];
    __shared__ float w_s[32][20];

    int b = blockIdx.x >> 5;             // 32 blocks per image (2 rows each)
    int h0 = (blockIdx.x & 31) * 2;
    int tid = threadIdx.x;
    int pp = tid & 63;                   // pixel slot (handles pp and pp+64)
    int g = tid >> 6;                    // oc group: oc = g + 4*j

    float acc[2][5] = {};

    for (int tap = 0; tap < 9; tap++) {
        int ky = tap / 3, kx = tap % 3;
        for (int c0 = 0; c0 < 128; c0 += 32) {
            // Stage A tile: 128 pixels x 32 cin, coalesced (lane = cin)
            #pragma unroll
            for (int i = 0; i < 16; i++) {
                int idx = tid + 256 * i;
                int c = idx & 31, p = idx >> 5;
                int y = h0 + (p >> 6) + ky - 1;
                int xx = (p & 63) + kx - 1;
                float v = 0.f;
                if ((unsigned)y < 64u && (unsigned)xx < 64u)
                    v = g_xt[(((b * 64 + y) * 64 + xx) << 7) + c0 + c];
                a_s[p][c] = v;
            }
            // Stage W tile: 32 cin x 18 oc (padded to 20 with zeros)
            #pragma unroll
            for (int i = 0; i < 3; i++) {
                int idx = tid + 256 * i;
                if (idx < 640) {
                    int c = idx / 20, oc = idx % 20;
                    w_s[c][oc] = (oc < 18)
                        ? g_woT[(tap * 128 + c0 + c) * 18 + oc] : 0.f;
                }
            }
            __syncthreads();
            #pragma unroll
            for (int c = 0; c < 32; c++) {
                float a0 = a_s[pp][c];
                float a1 = a_s[pp + 64][c];
                #pragma unroll
                for (int j = 0; j < 5; j++) {
                    float wv = w_s[c][g + 4 * j];
                    acc[0][j] += a0 * wv;
                    acc[1][j] += a1 * wv;
                }
            }
            __syncthreads();
        }
    }
    #pragma unroll
    for (int r = 0; r < 2; r++) {
        int p = pp + 64 * r;
        int h = h0 + (p >> 6), w = p & 63;
        #pragma unroll
        for (int j = 0; j < 5; j++) {
            int oc = g + 4 * j;
            if (oc < 18)
                g_off[((b * 18 + oc) * 64 + h) * 64 + w] = acc[r][j];
        }
    }
}

// ---------------------------------------------------------------------------
// Deformable conv: block = 32 pixels x 128 outputs, 256 threads.
// Reduction: 9 taps x 4 cin-chunks of 32.
// Gather is 128B-coalesced across cin (NHWC x), with uniform weight-zero skip.
// ---------------------------------------------------------------------------
__global__ __launch_bounds__(256) void deform_kernel(float* __restrict__ out) {
    __shared__ float w_s[32][128];   // [cin_chunk][o]
    __shared__ float v_s[32][36];    // [pixel][cin_chunk] (padded, float4-aligned)
    __shared__ float cw[4][32];      // per-corner bilinear weights (0 if OOB)
    __shared__ int   coff[4][32];    // per-corner clamped (y*64+x)*128 offsets

    int b = blockIdx.x >> 7;
    int pix0 = (blockIdx.x & 127) * 32;
    int tid = threadIdx.x;
    int lane = tid & 31;
    int warp = tid >> 5;
    int tx = tid & 31;               // out group: o = tx*4..tx*4+3
    int ty = tid >> 5;               // pix group: p = ty*4..ty*4+3

    const float* xb = g_xt + (size_t)b * HW * C_IN;
    float acc[4][4] = {};

    for (int k = 0; k < 9; k++) {
        // Per-(pixel, tap) sampling setup by warp 0 (lane = pixel)
        if (warp == 0) {
            int p = lane;
            int gp = pix0 + p;
            int h = gp >> 6, w = gp & 63;
            float dy = g_off[((b * 18 + 2 * k) * 64 + h) * 64 + w];
            float dx = g_off[((b * 18 + 2 * k + 1) * 64 + h) * 64 + w];
            float py = (float)(h - 1 + k / 3) + dy;
            float px = (float)(w - 1 + k % 3) + dx;
            float y0f = floorf(py), x0f = floorf(px);
            float fy = py - y0f, fx = px - x0f;
            #pragma unroll
            for (int j = 0; j < 4; j++) {
                float yf = y0f + (float)(j >> 1);
                float xf = x0f + (float)(j & 1);
                bool ok = (yf >= 0.f && yf < 64.f && xf >= 0.f && xf < 64.f);
                float wy = (j >> 1) ? fy : 1.f - fy;
                float wx = (j & 1) ? fx : 1.f - fx;
                cw[j][p] = ok ? wy * wx : 0.f;
                int yi = (int)fminf(fmaxf(yf, 0.f), 63.f);
                int xi = (int)fminf(fmaxf(xf, 0.f), 63.f);
                coff[j][p] = ((yi << 6) + xi) << 7;
            }
        }
        __syncthreads();

        for (int c0 = 0; c0 < 128; c0 += 32) {
            // Stage W: 32 cin x 128 o, coalesced (lane = o)
            #pragma unroll
            for (int i = 0; i < 16; i++) {
                int idx = tid + 256 * i;
                int c = idx >> 7, o = idx & 127;
                w_s[c][o] = g_wT[(k * 128 + c0 + c) * 128 + o];
            }
            // Gather V: warp handles 4 pixels, lane = cin within chunk.
            // Each corner load is a 128B coalesced read; branch is warp-uniform.
            #pragma unroll
            for (int pp = 0; pp < 4; pp++) {
                int p = warp * 4 + pp;
                float a = 0.f;
                #pragma unroll
                for (int j = 0; j < 4; j++) {
                    float wgt = cw[j][p];
                    if (wgt != 0.f)
                        a += wgt * xb[coff[j][p] + c0 + lane];
                }
                v_s[p][lane] = a;
            }
            __syncthreads();

            // MMA: 4 pix x 4 out per thread, float4 smem loads
            #pragma unroll
            for (int c4 = 0; c4 < 8; c4++) {
                float vloc[4][4];
                #pragma unroll
                for (int pp = 0; pp < 4; pp++) {
                    float4 t = *(const float4*)&v_s[ty * 4 + pp][c4 * 4];
                    vloc[pp][0] = t.x; vloc[pp][1] = t.y;
                    vloc[pp][2] = t.z; vloc[pp][3] = t.w;
                }
                #pragma unroll
                for (int cc = 0; cc < 4; cc++) {
                    float4 wv = *(const float4*)&w_s[c4 * 4 + cc][tx * 4];
                    #pragma unroll
                    for (int pp = 0; pp < 4; pp++) {
                        acc[pp][0] += vloc[pp][cc] * wv.x;
                        acc[pp][1] += vloc[pp][cc] * wv.y;
                        acc[pp][2] += vloc[pp][cc] * wv.z;
                        acc[pp][3] += vloc[pp][cc] * wv.w;
                    }
                }
            }
            __syncthreads();
        }
    }

    // Store out[b][o][h][w]
    #pragma unroll
    for (int pp = 0; pp < 4; pp++) {
        int gp = pix0 + ty * 4 + pp;
        int h = gp >> 6, w = gp & 63;
        #pragma unroll
        for (int oo = 0; oo < 4; oo++) {
            int o = tx * 4 + oo;
            out[(((b * 128 + o) * 64 + h) << 6) + w] = acc[pp][oo];
        }
    }
}

// ---------------------------------------------------------------------------
extern "C" void kernel_launch(void* const* d_in, const int* in_sizes, int n_in,
                              void* d_out, int out_size) {
    const float* x  = (const float*)d_in[0];
    const float* wo = (const float*)d_in[1];   // w_offset
    const float* wc = (const float*)d_in[2];   // w_conv
    float* out = (float*)d_out;

    dim3 tpb(32, 8);
    transpose_x_kernel<<<dim3(HW / 32, C_IN / 32, Bn), tpb>>>(x);
    transpose_w_kernel<<<(K2 * C_IN * C_OUT + 255) / 256, 256>>>(wo, wc);
    offset_conv_kernel<<<Bn * (HH / 2), 256>>>();
    deform_kernel<<<Bn * (HW / 32), 256>>>(out);
}